// round 3
// baseline (speedup 1.0000x reference)
#include <cuda_runtime.h>

// Problem constants (fixed shapes from reference setup_inputs)
#define NN 50000
#define EE 800000
#define GG 64
#define HH 64
#define LL 3
#define CC 4
#define NH (NN*HH)

// ---------------------------------------------------------------------------
// Scratch (no allocations allowed — __device__ globals)
// ---------------------------------------------------------------------------
__device__ float g_x[NH];          // working node features (copy of input x)
__device__ float g_h[NH];          // intermediate h1 per step
__device__ int   g_rowptr[NN+1];   // CSR row pointers keyed by dst
__device__ int   g_cursor[NN];     // degree counts, then fill cursors
__device__ int   g_csrc[EE];       // CSR src indices
__device__ float g_stats[LL*CC*128]; // per-(t,c) [sum(64) | sumsq(64)]
__device__ float g_z[GG*HH*LL];    // pooled [G, H*L]
__device__ int   g_ccnt[CC];       // cluster sizes
__device__ int   g_is64;           // 1 if index tensors are int64, 0 if int32

// Index load honoring runtime dtype flag
__device__ __forceinline__ int load_idx(const void* p, long long i, int is64) {
    if (is64) return (int)((const long long*)p)[i];
    return ((const int*)p)[i];
}

// ---------------------------------------------------------------------------
// Detect index dtype: int64 little-endian => odd int32 words are zero high-halves
// ---------------------------------------------------------------------------
__global__ void detect_kernel(const void* eidx) {
    if (threadIdx.x == 0 && blockIdx.x == 0) {
        const int* e32 = (const int*)eidx;
        int all0 = 1;
        for (int k = 0; k < 1024; ++k) {
            if (e32[2 * k + 1] != 0) { all0 = 0; break; }
        }
        g_is64 = all0;
    }
}

// ---------------------------------------------------------------------------
// Init: copy x into scratch, zero counters/stats
// ---------------------------------------------------------------------------
__global__ void init_kernel(const float* __restrict__ x) {
    int idx = blockIdx.x * blockDim.x + threadIdx.x;
    if (idx < NH)         g_x[idx] = x[idx];
    if (idx < NN)         g_cursor[idx] = 0;
    if (idx < LL*CC*128)  g_stats[idx] = 0.f;
    if (idx < CC)         g_ccnt[idx] = 0;
}

// Count in-degree per dst node + cluster sizes
__global__ void count_kernel(const void* __restrict__ eidx,
                             const int* __restrict__ cl) {
    int is64 = g_is64;
    int i = blockIdx.x * blockDim.x + threadIdx.x;
    if (i < EE) {
        int d = load_idx(eidx, (long long)EE + i, is64);
        atomicAdd(&g_cursor[d], 1);
    } else if (i < EE + NN) {
        int n = i - EE;
        atomicAdd(&g_ccnt[cl[n]], 1);
    }
}

// Single-block exclusive scan of degrees -> rowptr (and cursor copy)
__global__ void scan_kernel() {
    __shared__ int part[1024];
    int tid = threadIdx.x;
    const int chunk = (NN + 1023) / 1024;
    int s0 = tid * chunk;
    int s1 = min(s0 + chunk, NN);
    int s = 0;
    for (int i = s0; i < s1; ++i) s += g_cursor[i];
    part[tid] = s;
    __syncthreads();
    if (tid == 0) {
        int acc = 0;
        for (int i = 0; i < 1024; ++i) { int t = part[i]; part[i] = acc; acc += t; }
        g_rowptr[NN] = acc;
    }
    __syncthreads();
    int acc = part[tid];
    for (int i = s0; i < s1; ++i) {
        int d = g_cursor[i];
        g_rowptr[i] = acc;
        g_cursor[i] = acc;
        acc += d;
    }
}

// Fill CSR: for each edge, append src into dst's row
__global__ void fill_kernel(const void* __restrict__ eidx) {
    int is64 = g_is64;
    int i = blockIdx.x * blockDim.x + threadIdx.x;
    if (i < EE) {
        int s = load_idx(eidx, i, is64);
        int d = load_idx(eidx, (long long)EE + i, is64);
        int pos = atomicAdd(&g_cursor[d], 1);
        g_csrc[pos] = s;
    }
}

// ---------------------------------------------------------------------------
// Step kernel 1: for masked nodes, h = (agg + x) @ W1 + b1; accumulate BN stats
// 256 threads = 4 row-groups of 64 feature-parallel threads
// ---------------------------------------------------------------------------
__global__ void gather_mm1_kernel(const int* __restrict__ cl,
                                  const float* __restrict__ W1,
                                  const float* __restrict__ b1,
                                  int tc, int c) {
    __shared__ float hsh[4][64];
    __shared__ float s1sh[64], s2sh[64];
    int tid = threadIdx.x;
    int sub = tid >> 6;
    int f   = tid & 63;

    const float* W = W1 + tc * 4096;
    float wcol[64];
#pragma unroll
    for (int i = 0; i < 64; ++i) wcol[i] = W[i * 64 + f];   // column f of W1
    float bias = b1[tc * 64 + f];
    if (tid < 64) { s1sh[tid] = 0.f; s2sh[tid] = 0.f; }
    __syncthreads();

    float a1 = 0.f, a2 = 0.f;
    int per = gridDim.x * 4;
    int niter = (NN + per - 1) / per;
    int base = blockIdx.x * 4 + sub;

    for (int it = 0; it < niter; ++it) {
        int node = base + it * per;
        bool valid = (node < NN) && (cl[node] == c);
        float acc = 0.f;
        if (valid) {
            acc = g_x[node * 64 + f];                  // residual (1+eps)*x, eps=0
            int e0 = g_rowptr[node], e1 = g_rowptr[node + 1];
            for (int e = e0; e < e1; ++e)
                acc += g_x[g_csrc[e] * 64 + f];        // gather, L2-resident
        }
        hsh[sub][f] = acc;
        __syncthreads();
        if (valid) {
            float o = bias;
#pragma unroll
            for (int i = 0; i < 64; ++i) o += hsh[sub][i] * wcol[i];
            g_h[node * 64 + f] = o;
            a1 += o; a2 += o * o;
        }
        __syncthreads();
    }
    atomicAdd(&s1sh[f], a1);
    atomicAdd(&s2sh[f], a2);
    __syncthreads();
    if (tid < 64) {
        atomicAdd(&g_stats[tc * 128 + tid],       s1sh[tid]);
        atomicAdd(&g_stats[tc * 128 + 64 + tid],  s2sh[tid]);
    }
}

// ---------------------------------------------------------------------------
// Step kernel 2: BN(apply) + ReLU + @W2 + b2 -> write masked rows back into x
// ---------------------------------------------------------------------------
__global__ void bn_mm2_kernel(const int* __restrict__ cl,
                              const float* __restrict__ g1,
                              const float* __restrict__ be1,
                              const float* __restrict__ W2,
                              const float* __restrict__ b2,
                              int tc, int c) {
    __shared__ float hsh[4][64];
    int tid = threadIdx.x;
    int sub = tid >> 6;
    int f   = tid & 63;

    float cnt  = (float)max(g_ccnt[c], 1);
    float sum  = g_stats[tc * 128 + f];
    float sq   = g_stats[tc * 128 + 64 + f];
    float mean = sum / cnt;
    float var  = sq / cnt - mean * mean;
    float inv  = rsqrtf(var + 1e-5f) * g1[tc * 64 + f];
    float beta = be1[tc * 64 + f];

    const float* W = W2 + tc * 4096;
    float wcol[64];
#pragma unroll
    for (int i = 0; i < 64; ++i) wcol[i] = W[i * 64 + f];
    float bias = b2[tc * 64 + f];

    int per = gridDim.x * 4;
    int niter = (NN + per - 1) / per;
    int base = blockIdx.x * 4 + sub;

    for (int it = 0; it < niter; ++it) {
        int node = base + it * per;
        bool valid = (node < NN) && (cl[node] == c);
        float v = 0.f;
        if (valid) {
            v = g_h[node * 64 + f];
            v = (v - mean) * inv + beta;
            v = fmaxf(v, 0.f);
        }
        hsh[sub][f] = v;
        __syncthreads();
        if (valid) {
            float o = bias;
#pragma unroll
            for (int i = 0; i < 64; ++i) o += hsh[sub][i] * wcol[i];
            g_x[node * 64 + f] = o;
        }
        __syncthreads();
    }
}

// ---------------------------------------------------------------------------
// Graph pooling: batch is SORTED -> block g binary-searches its row range,
// 64 threads do a conflict-free column sum. No atomics.
// ---------------------------------------------------------------------------
__global__ void pool_kernel(const void* __restrict__ batch, int t) {
    __shared__ int lohi[2];
    int is64 = g_is64;
    int g = blockIdx.x;
    int tid = threadIdx.x;
    if (tid < 2) {
        int target = g + tid;
        int lo = 0, hi = NN;
        while (lo < hi) {
            int m = (lo + hi) >> 1;
            if (load_idx(batch, m, is64) < target) lo = m + 1; else hi = m;
        }
        lohi[tid] = lo;
    }
    __syncthreads();
    int lo = lohi[0], hi = lohi[1];
    float s = 0.f;
    for (int r = lo; r < hi; ++r) s += g_x[r * 64 + tid];
    g_z[g * (HH * LL) + t * 64 + tid] = s;
}

// ---------------------------------------------------------------------------
// Head: z[64,192] @ Wp1 + bp1 -> BN -> ReLU -> @ Wp2 + bp2 -> out[64,64]
// ---------------------------------------------------------------------------
__global__ void final_kernel(const float* __restrict__ Wp1, const float* __restrict__ bp1,
                             const float* __restrict__ gp,  const float* __restrict__ bep,
                             const float* __restrict__ Wp2, const float* __restrict__ bp2,
                             float* __restrict__ out) {
    __shared__ float h1[GG * 64];
    __shared__ float msh[64], ish[64];
    int tid = threadIdx.x;

    for (int idx = tid; idx < GG * 64; idx += blockDim.x) {
        int g = idx >> 6, j = idx & 63;
        float s = bp1[j];
        for (int k = 0; k < HH * LL; ++k) s += g_z[g * (HH * LL) + k] * Wp1[k * 64 + j];
        h1[idx] = s;
    }
    __syncthreads();
    if (tid < 64) {
        float s = 0.f, q = 0.f;
        for (int g = 0; g < GG; ++g) { float v = h1[g * 64 + tid]; s += v; q += v * v; }
        float mean = s / (float)GG;
        float var  = q / (float)GG - mean * mean;
        msh[tid] = mean;
        ish[tid] = rsqrtf(var + 1e-5f) * gp[tid];
    }
    __syncthreads();
    for (int idx = tid; idx < GG * 64; idx += blockDim.x) {
        int j = idx & 63;
        h1[idx] = fmaxf((h1[idx] - msh[j]) * ish[j] + bep[j], 0.f);
    }
    __syncthreads();
    for (int idx = tid; idx < GG * 64; idx += blockDim.x) {
        int g = idx >> 6, j = idx & 63;
        float s = bp2[j];
#pragma unroll
        for (int k = 0; k < 64; ++k) s += h1[g * 64 + k] * Wp2[k * 64 + j];
        out[g * 64 + j] = s;
    }
}

// ---------------------------------------------------------------------------
// Launch
// ---------------------------------------------------------------------------
extern "C" void kernel_launch(void* const* d_in, const int* in_sizes, int n_in,
                              void* d_out, int out_size) {
    const float* x     = (const float*)d_in[0];
    const int*   cl    = (const int*)d_in[1];
    const void*  eidx  = d_in[2];              // int32 or int64, detected on device
    const void*  batch = d_in[3];
    const float* W1  = (const float*)d_in[4];
    const float* b1  = (const float*)d_in[5];
    const float* g1  = (const float*)d_in[6];
    const float* be1 = (const float*)d_in[7];
    const float* W2  = (const float*)d_in[8];
    const float* b2  = (const float*)d_in[9];
    const float* Wp1 = (const float*)d_in[10];
    const float* bp1 = (const float*)d_in[11];
    const float* gp  = (const float*)d_in[12];
    const float* bep = (const float*)d_in[13];
    const float* Wp2 = (const float*)d_in[14];
    const float* bp2 = (const float*)d_in[15];
    float* out = (float*)d_out;

    detect_kernel<<<1, 32>>>(eidx);
    init_kernel <<<(NH + 255) / 256, 256>>>(x);
    count_kernel<<<(EE + NN + 255) / 256, 256>>>(eidx, cl);
    scan_kernel <<<1, 1024>>>();
    fill_kernel <<<(EE + 255) / 256, 256>>>(eidx);

    for (int t = 0; t < LL; ++t) {
        for (int c = 0; c < CC; ++c) {
            int tc = t * CC + c;
            gather_mm1_kernel<<<512, 256>>>(cl, W1, b1, tc, c);
            bn_mm2_kernel    <<<512, 256>>>(cl, g1, be1, W2, b2, tc, c);
        }
        pool_kernel<<<GG, 64>>>(batch, t);
    }
    final_kernel<<<1, 256>>>(Wp1, bp1, gp, bep, Wp2, bp2, out);
}

// round 4
// speedup vs baseline: 1.9621x; 1.9621x over previous
#include <cuda_runtime.h>

#define NN 50000
#define EE 800000
#define GG 64
#define HH 64
#define LL 3
#define CC 4
#define NH (NN*HH)
#define SCAN_BLK 200          // ceil(50000/256) = 196 -> use 200
#define STEP_GRID 1024        // blocks for step kernels

// ---------------------------------------------------------------------------
// Scratch
// ---------------------------------------------------------------------------
__device__ float g_x[NH];
__device__ float g_h[NH];
__device__ int   g_rowptr[NN+1];
__device__ int   g_cursor[NN];
__device__ int   g_deg[NN];
__device__ int   g_csrc[EE];
__device__ float g_stats[LL*CC*128];
__device__ float g_z[GG*HH*LL];
__device__ int   g_ccnt[CC];
__device__ int   g_coff[CC+1];
__device__ int   g_ccur[CC];
__device__ int   g_clist[NN];      // nodes grouped by cluster
__device__ int   g_bsum[SCAN_BLK];
__device__ int   g_boff[SCAN_BLK];
__device__ int   g_is64;

__device__ __forceinline__ int load_idx(const void* p, long long i, int is64) {
    if (is64) return (int)((const long long*)p)[i];
    return ((const int*)p)[i];
}

__device__ __forceinline__ void bar64(int id) {
    asm volatile("bar.sync %0, 64;" :: "r"(id) : "memory");
}

// ---------------------------------------------------------------------------
__global__ void detect_kernel(const void* eidx) {
    if (threadIdx.x == 0 && blockIdx.x == 0) {
        const int* e32 = (const int*)eidx;
        int all0 = 1;
        for (int k = 0; k < 1024; ++k)
            if (e32[2 * k + 1] != 0) { all0 = 0; break; }
        g_is64 = all0;
    }
}

__global__ void init_kernel(const float* __restrict__ x) {
    int idx = blockIdx.x * blockDim.x + threadIdx.x;
    if (idx < NH)         g_x[idx] = x[idx];
    if (idx < NN)         g_deg[idx] = 0;
    if (idx < LL*CC*128)  g_stats[idx] = 0.f;
    if (idx < CC)         g_ccnt[idx] = 0;
}

// Count in-degree per dst + cluster sizes
__global__ void count_kernel(const void* __restrict__ eidx,
                             const int* __restrict__ cl) {
    int is64 = g_is64;
    int i = blockIdx.x * blockDim.x + threadIdx.x;
    if (i < EE) {
        int d = load_idx(eidx, (long long)EE + i, is64);
        atomicAdd(&g_deg[d], 1);
    } else if (i < EE + NN) {
        atomicAdd(&g_ccnt[cl[i - EE]], 1);
    }
}

// Tiny cluster-offset scan (4 entries)
__global__ void cscan_kernel() {
    if (threadIdx.x == 0) {
        int acc = 0;
        for (int c = 0; c < CC; ++c) {
            g_coff[c] = acc; g_ccur[c] = acc; acc += g_ccnt[c];
        }
        g_coff[CC] = acc;
    }
}

__global__ void clist_kernel(const int* __restrict__ cl) {
    int i = blockIdx.x * blockDim.x + threadIdx.x;
    if (i < NN) {
        int pos = atomicAdd(&g_ccur[cl[i]], 1);
        g_clist[pos] = i;
    }
}

// --- 3-level parallel scan of degrees -> rowptr + cursor ---
__global__ void blocksum_kernel() {
    __shared__ int sh[256];
    int b = blockIdx.x, tid = threadIdx.x;
    int idx = b * 256 + tid;
    sh[tid] = (idx < NN) ? g_deg[idx] : 0;
    __syncthreads();
    for (int s = 128; s > 0; s >>= 1) {
        if (tid < s) sh[tid] += sh[tid + s];
        __syncthreads();
    }
    if (tid == 0) g_bsum[b] = sh[0];
}

__global__ void scansmall_kernel() {
    __shared__ int sh[SCAN_BLK];
    int tid = threadIdx.x;
    if (tid < SCAN_BLK) sh[tid] = g_bsum[tid];
    __syncthreads();
    if (tid == 0) {
        int acc = 0;
        for (int i = 0; i < SCAN_BLK; ++i) { int t = sh[i]; g_boff[i] = acc; acc += t; }
        g_rowptr[NN] = acc;
    }
}

__global__ void rowptr_kernel() {
    __shared__ int sh[256];
    int b = blockIdx.x, tid = threadIdx.x;
    int idx = b * 256 + tid;
    int v = (idx < NN) ? g_deg[idx] : 0;
    sh[tid] = v;
    __syncthreads();
    // Hillis-Steele inclusive scan
    for (int s = 1; s < 256; s <<= 1) {
        int t = (tid >= s) ? sh[tid - s] : 0;
        __syncthreads();
        sh[tid] += t;
        __syncthreads();
    }
    if (idx < NN) {
        int excl = g_boff[b] + sh[tid] - v;
        g_rowptr[idx] = excl;
        g_cursor[idx] = excl;
    }
}

__global__ void fill_kernel(const void* __restrict__ eidx) {
    int is64 = g_is64;
    int i = blockIdx.x * blockDim.x + threadIdx.x;
    if (i < EE) {
        int s = load_idx(eidx, i, is64);
        int d = load_idx(eidx, (long long)EE + i, is64);
        int pos = atomicAdd(&g_cursor[d], 1);
        g_csrc[pos] = s;
    }
}

// ---------------------------------------------------------------------------
// Step kernel 1: masked nodes only (via g_clist): h = (agg + x) @ W1 + b1
// 256 threads = 4 groups of 64; per-group named barriers only.
// ---------------------------------------------------------------------------
__global__ void gather_mm1_kernel(const float* __restrict__ W1,
                                  const float* __restrict__ b1,
                                  int tc, int c) {
    __shared__ float hsh[4][64];
    __shared__ float s1sh[64], s2sh[64];
    int tid = threadIdx.x;
    int sub = tid >> 6;
    int f   = tid & 63;

    const float* W = W1 + tc * 4096;
    float wcol[64];
#pragma unroll
    for (int i = 0; i < 64; ++i) wcol[i] = W[i * 64 + f];
    float bias = b1[tc * 64 + f];
    if (tid < 64) { s1sh[tid] = 0.f; s2sh[tid] = 0.f; }
    __syncthreads();

    int lo = g_coff[c], hi = g_coff[c + 1];
    int cnt = hi - lo;
    int per = gridDim.x * 4;
    int base = blockIdx.x * 4 + sub;

    float a1 = 0.f, a2 = 0.f;
    for (int pos = base; pos < cnt; pos += per) {
        int node = g_clist[lo + pos];
        // gather with 4-way MLP
        float acc0 = g_x[node * 64 + f], acc1 = 0.f, acc2 = 0.f, acc3 = 0.f;
        int e0 = g_rowptr[node], e1 = g_rowptr[node + 1];
        int e = e0;
        for (; e + 4 <= e1; e += 4) {
            int s0 = g_csrc[e], s1 = g_csrc[e+1], s2 = g_csrc[e+2], s3 = g_csrc[e+3];
            acc0 += g_x[s0 * 64 + f];
            acc1 += g_x[s1 * 64 + f];
            acc2 += g_x[s2 * 64 + f];
            acc3 += g_x[s3 * 64 + f];
        }
        for (; e < e1; ++e) acc0 += g_x[g_csrc[e] * 64 + f];
        hsh[sub][f] = (acc0 + acc1) + (acc2 + acc3);
        bar64(sub + 1);
        float o = bias;
#pragma unroll
        for (int i = 0; i < 64; ++i) o += hsh[sub][i] * wcol[i];
        g_h[node * 64 + f] = o;
        a1 += o; a2 += o * o;
        bar64(sub + 1);
    }
    atomicAdd(&s1sh[f], a1);
    atomicAdd(&s2sh[f], a2);
    __syncthreads();
    if (tid < 64) {
        atomicAdd(&g_stats[tc * 128 + tid],      s1sh[tid]);
        atomicAdd(&g_stats[tc * 128 + 64 + tid], s2sh[tid]);
    }
}

// ---------------------------------------------------------------------------
// Step kernel 2: BN + ReLU + @W2 + b2 -> write back masked rows
// ---------------------------------------------------------------------------
__global__ void bn_mm2_kernel(const float* __restrict__ g1,
                              const float* __restrict__ be1,
                              const float* __restrict__ W2,
                              const float* __restrict__ b2,
                              int tc, int c) {
    __shared__ float hsh[4][64];
    int tid = threadIdx.x;
    int sub = tid >> 6;
    int f   = tid & 63;

    float cnt_f = (float)max(g_ccnt[c], 1);
    float mean  = g_stats[tc * 128 + f] / cnt_f;
    float var   = g_stats[tc * 128 + 64 + f] / cnt_f - mean * mean;
    float inv   = rsqrtf(var + 1e-5f) * g1[tc * 64 + f];
    float beta  = be1[tc * 64 + f];

    const float* W = W2 + tc * 4096;
    float wcol[64];
#pragma unroll
    for (int i = 0; i < 64; ++i) wcol[i] = W[i * 64 + f];
    float bias = b2[tc * 64 + f];

    int lo = g_coff[c], hi = g_coff[c + 1];
    int cnt = hi - lo;
    int per = gridDim.x * 4;
    int base = blockIdx.x * 4 + sub;

    for (int pos = base; pos < cnt; pos += per) {
        int node = g_clist[lo + pos];
        float v = g_h[node * 64 + f];
        v = fmaxf((v - mean) * inv + beta, 0.f);
        hsh[sub][f] = v;
        bar64(sub + 1);
        float o = bias;
#pragma unroll
        for (int i = 0; i < 64; ++i) o += hsh[sub][i] * wcol[i];
        g_x[node * 64 + f] = o;
        bar64(sub + 1);
    }
}

// ---------------------------------------------------------------------------
// Pooling: batch sorted -> block g binary-searches its row range
// ---------------------------------------------------------------------------
__global__ void pool_kernel(const void* __restrict__ batch, int t) {
    __shared__ int lohi[2];
    int is64 = g_is64;
    int g = blockIdx.x;
    int tid = threadIdx.x;
    if (tid < 2) {
        int target = g + tid;
        int lo = 0, hi = NN;
        while (lo < hi) {
            int m = (lo + hi) >> 1;
            if (load_idx(batch, m, is64) < target) lo = m + 1; else hi = m;
        }
        lohi[tid] = lo;
    }
    __syncthreads();
    int lo = lohi[0], hi = lohi[1];
    float s = 0.f;
    for (int r = lo; r < hi; ++r) s += g_x[r * 64 + tid];
    g_z[g * (HH * LL) + t * 64 + tid] = s;
}

// ---------------------------------------------------------------------------
// Head
// ---------------------------------------------------------------------------
__global__ void final_kernel(const float* __restrict__ Wp1, const float* __restrict__ bp1,
                             const float* __restrict__ gp,  const float* __restrict__ bep,
                             const float* __restrict__ Wp2, const float* __restrict__ bp2,
                             float* __restrict__ out) {
    __shared__ float h1[GG * 64];
    __shared__ float msh[64], ish[64];
    int tid = threadIdx.x;

    for (int idx = tid; idx < GG * 64; idx += blockDim.x) {
        int g = idx >> 6, j = idx & 63;
        float s = bp1[j];
        for (int k = 0; k < HH * LL; ++k) s += g_z[g * (HH * LL) + k] * Wp1[k * 64 + j];
        h1[idx] = s;
    }
    __syncthreads();
    if (tid < 64) {
        float s = 0.f, q = 0.f;
        for (int g = 0; g < GG; ++g) { float v = h1[g * 64 + tid]; s += v; q += v * v; }
        float mean = s / (float)GG;
        float var  = q / (float)GG - mean * mean;
        msh[tid] = mean;
        ish[tid] = rsqrtf(var + 1e-5f) * gp[tid];
    }
    __syncthreads();
    for (int idx = tid; idx < GG * 64; idx += blockDim.x) {
        int j = idx & 63;
        h1[idx] = fmaxf((h1[idx] - msh[j]) * ish[j] + bep[j], 0.f);
    }
    __syncthreads();
    for (int idx = tid; idx < GG * 64; idx += blockDim.x) {
        int g = idx >> 6, j = idx & 63;
        float s = bp2[j];
#pragma unroll
        for (int k = 0; k < 64; ++k) s += h1[g * 64 + k] * Wp2[k * 64 + j];
        out[g * 64 + j] = s;
    }
}

// ---------------------------------------------------------------------------
extern "C" void kernel_launch(void* const* d_in, const int* in_sizes, int n_in,
                              void* d_out, int out_size) {
    const float* x     = (const float*)d_in[0];
    const int*   cl    = (const int*)d_in[1];
    const void*  eidx  = d_in[2];
    const void*  batch = d_in[3];
    const float* W1  = (const float*)d_in[4];
    const float* b1  = (const float*)d_in[5];
    const float* g1  = (const float*)d_in[6];
    const float* be1 = (const float*)d_in[7];
    const float* W2  = (const float*)d_in[8];
    const float* b2  = (const float*)d_in[9];
    const float* Wp1 = (const float*)d_in[10];
    const float* bp1 = (const float*)d_in[11];
    const float* gp  = (const float*)d_in[12];
    const float* bep = (const float*)d_in[13];
    const float* Wp2 = (const float*)d_in[14];
    const float* bp2 = (const float*)d_in[15];
    float* out = (float*)d_out;

    detect_kernel<<<1, 32>>>(eidx);
    init_kernel  <<<(NH + 255) / 256, 256>>>(x);
    count_kernel <<<(EE + NN + 255) / 256, 256>>>(eidx, cl);
    cscan_kernel <<<1, 32>>>();
    clist_kernel <<<(NN + 255) / 256, 256>>>(cl);
    blocksum_kernel <<<SCAN_BLK, 256>>>();
    scansmall_kernel<<<1, 256>>>();
    rowptr_kernel   <<<SCAN_BLK, 256>>>();
    fill_kernel  <<<(EE + 255) / 256, 256>>>(eidx);

    for (int t = 0; t < LL; ++t) {
        for (int c = 0; c < CC; ++c) {
            int tc = t * CC + c;
            gather_mm1_kernel<<<STEP_GRID, 256>>>(W1, b1, tc, c);
            bn_mm2_kernel    <<<STEP_GRID, 256>>>(g1, be1, W2, b2, tc, c);
        }
        pool_kernel<<<GG, 64>>>(batch, t);
    }
    final_kernel<<<1, 256>>>(Wp1, bp1, gp, bep, Wp2, bp2, out);
}

// round 5
// speedup vs baseline: 2.3386x; 1.1919x over previous
#include <cuda_runtime.h>

#define NN 50000
#define EE 800000
#define GG 64
#define HH 64
#define LL 3
#define CC 4
#define NH (NN*HH)
#define SCAN_BLK 200
#define STEP_GRID 512

// ---------------------------------------------------------------------------
// Scratch
// ---------------------------------------------------------------------------
__device__ float g_x[NH];
__device__ float g_h[NH];
__device__ int   g_rowptr[NN+1];
__device__ int   g_cursor[NN];
__device__ int   g_deg[NN];
__device__ int   g_csrc[EE];
__device__ float g_stats[LL*CC*128];
__device__ float g_z[GG*HH*LL];
__device__ int   g_ccnt[CC];
__device__ int   g_coff[CC+1];
__device__ int   g_ccur[CC];
__device__ int   g_clist[NN];
__device__ int   g_bsum[SCAN_BLK];
__device__ int   g_boff[SCAN_BLK];
__device__ int   g_is64;

__device__ __forceinline__ int load_idx(const void* p, long long i, int is64) {
    if (is64) return (int)((const long long*)p)[i];
    return ((const int*)p)[i];
}

__device__ __forceinline__ void bar64(int id) {
    asm volatile("bar.sync %0, 64;" :: "r"(id) : "memory");
}

// ---------------------------------------------------------------------------
__global__ void detect_kernel(const void* eidx) {
    if (threadIdx.x == 0 && blockIdx.x == 0) {
        const int* e32 = (const int*)eidx;
        int all0 = 1;
        for (int k = 0; k < 1024; ++k)
            if (e32[2 * k + 1] != 0) { all0 = 0; break; }
        g_is64 = all0;
    }
}

__global__ void init_kernel(const float* __restrict__ x) {
    int idx = blockIdx.x * blockDim.x + threadIdx.x;
    if (idx < NH)         g_x[idx] = x[idx];
    if (idx < NN)         g_deg[idx] = 0;
    if (idx < LL*CC*128)  g_stats[idx] = 0.f;
    if (idx < CC)         g_ccnt[idx] = 0;
}

__global__ void count_kernel(const void* __restrict__ eidx,
                             const int* __restrict__ cl) {
    int is64 = g_is64;
    int i = blockIdx.x * blockDim.x + threadIdx.x;
    if (i < EE) {
        int d = load_idx(eidx, (long long)EE + i, is64);
        atomicAdd(&g_deg[d], 1);
    } else if (i < EE + NN) {
        atomicAdd(&g_ccnt[cl[i - EE]], 1);
    }
}

__global__ void cscan_kernel() {
    if (threadIdx.x == 0) {
        int acc = 0;
        for (int c = 0; c < CC; ++c) {
            g_coff[c] = acc; g_ccur[c] = acc; acc += g_ccnt[c];
        }
        g_coff[CC] = acc;
    }
}

__global__ void clist_kernel(const int* __restrict__ cl) {
    int i = blockIdx.x * blockDim.x + threadIdx.x;
    if (i < NN) {
        int pos = atomicAdd(&g_ccur[cl[i]], 1);
        g_clist[pos] = i;
    }
}

__global__ void blocksum_kernel() {
    __shared__ int sh[256];
    int b = blockIdx.x, tid = threadIdx.x;
    int idx = b * 256 + tid;
    sh[tid] = (idx < NN) ? g_deg[idx] : 0;
    __syncthreads();
    for (int s = 128; s > 0; s >>= 1) {
        if (tid < s) sh[tid] += sh[tid + s];
        __syncthreads();
    }
    if (tid == 0) g_bsum[b] = sh[0];
}

__global__ void scansmall_kernel() {
    __shared__ int sh[SCAN_BLK];
    int tid = threadIdx.x;
    if (tid < SCAN_BLK) sh[tid] = g_bsum[tid];
    __syncthreads();
    if (tid == 0) {
        int acc = 0;
        for (int i = 0; i < SCAN_BLK; ++i) { int t = sh[i]; g_boff[i] = acc; acc += t; }
        g_rowptr[NN] = acc;
    }
}

__global__ void rowptr_kernel() {
    __shared__ int sh[256];
    int b = blockIdx.x, tid = threadIdx.x;
    int idx = b * 256 + tid;
    int v = (idx < NN) ? g_deg[idx] : 0;
    sh[tid] = v;
    __syncthreads();
    for (int s = 1; s < 256; s <<= 1) {
        int t = (tid >= s) ? sh[tid - s] : 0;
        __syncthreads();
        sh[tid] += t;
        __syncthreads();
    }
    if (idx < NN) {
        int excl = g_boff[b] + sh[tid] - v;
        g_rowptr[idx] = excl;
        g_cursor[idx] = excl;
    }
}

__global__ void fill_kernel(const void* __restrict__ eidx) {
    int is64 = g_is64;
    int i = blockIdx.x * blockDim.x + threadIdx.x;
    if (i < EE) {
        int s = load_idx(eidx, i, is64);
        int d = load_idx(eidx, (long long)EE + i, is64);
        int pos = atomicAdd(&g_cursor[d], 1);
        g_csrc[pos] = s;
    }
}

// ---------------------------------------------------------------------------
// Step kernel 1: h = (agg + x) @ W1 + b1 over cluster-c nodes; BN stat accum.
// 256 threads = 4 groups of 64. W staged via shared. Edge idx staged in shared.
// ---------------------------------------------------------------------------
__global__ void gather_mm1_kernel(const float* __restrict__ W1,
                                  const float* __restrict__ b1,
                                  int tc, int c) {
    __shared__ float Wsh[4096];
    __shared__ float hsh[4][64];
    __shared__ int   esh[4][64];
    __shared__ float s1sh[64], s2sh[64];
    int tid = threadIdx.x;
    int sub = tid >> 6;
    int f   = tid & 63;

    const float* W = W1 + tc * 4096;
    for (int i = tid; i < 4096; i += 256) Wsh[i] = W[i];       // coalesced
    if (tid < 64) { s1sh[tid] = 0.f; s2sh[tid] = 0.f; }
    __syncthreads();

    float wcol[64];
#pragma unroll
    for (int i = 0; i < 64; ++i) wcol[i] = Wsh[i * 64 + f];    // conflict-free LDS
    float bias = b1[tc * 64 + f];

    int lo = g_coff[c], hi = g_coff[c + 1];
    int cnt = hi - lo;
    int per = gridDim.x * 4;
    int base = blockIdx.x * 4 + sub;

    float a1 = 0.f, a2 = 0.f;
    for (int pos = base; pos < cnt; pos += per) {
        int node = g_clist[lo + pos];
        int e0 = g_rowptr[node], e1 = g_rowptr[node + 1];
        float acc0 = g_x[node * 64 + f];
        float acc1 = 0.f, acc2 = 0.f, acc3 = 0.f;
        float acc4 = 0.f, acc5 = 0.f, acc6 = 0.f, acc7 = 0.f;
        for (int chunk = e0; chunk < e1; chunk += 64) {
            int m = min(64, e1 - chunk);
            if (f < m) esh[sub][f] = g_csrc[chunk + f];
            bar64(sub + 1);
            int i = 0;
            for (; i + 8 <= m; i += 8) {
                int s0 = esh[sub][i+0], s1 = esh[sub][i+1];
                int s2 = esh[sub][i+2], s3 = esh[sub][i+3];
                int s4 = esh[sub][i+4], s5 = esh[sub][i+5];
                int s6 = esh[sub][i+6], s7 = esh[sub][i+7];
                acc0 += g_x[s0 * 64 + f];
                acc1 += g_x[s1 * 64 + f];
                acc2 += g_x[s2 * 64 + f];
                acc3 += g_x[s3 * 64 + f];
                acc4 += g_x[s4 * 64 + f];
                acc5 += g_x[s5 * 64 + f];
                acc6 += g_x[s6 * 64 + f];
                acc7 += g_x[s7 * 64 + f];
            }
            for (; i < m; ++i) acc0 += g_x[esh[sub][i] * 64 + f];
            bar64(sub + 1);
        }
        hsh[sub][f] = ((acc0 + acc1) + (acc2 + acc3)) + ((acc4 + acc5) + (acc6 + acc7));
        bar64(sub + 1);
        float o = bias;
#pragma unroll
        for (int i = 0; i < 64; ++i) o += hsh[sub][i] * wcol[i];
        g_h[node * 64 + f] = o;
        a1 += o; a2 += o * o;
        bar64(sub + 1);
    }
    atomicAdd(&s1sh[f], a1);
    atomicAdd(&s2sh[f], a2);
    __syncthreads();
    if (tid < 64) {
        atomicAdd(&g_stats[tc * 128 + tid],      s1sh[tid]);
        atomicAdd(&g_stats[tc * 128 + 64 + tid], s2sh[tid]);
    }
}

// ---------------------------------------------------------------------------
// Step kernel 2: BN + ReLU + @W2 + b2 -> write back masked rows
// ---------------------------------------------------------------------------
__global__ void bn_mm2_kernel(const float* __restrict__ g1,
                              const float* __restrict__ be1,
                              const float* __restrict__ W2,
                              const float* __restrict__ b2,
                              int tc, int c) {
    __shared__ float Wsh[4096];
    __shared__ float hsh[4][64];
    int tid = threadIdx.x;
    int sub = tid >> 6;
    int f   = tid & 63;

    const float* W = W2 + tc * 4096;
    for (int i = tid; i < 4096; i += 256) Wsh[i] = W[i];
    __syncthreads();

    float wcol[64];
#pragma unroll
    for (int i = 0; i < 64; ++i) wcol[i] = Wsh[i * 64 + f];
    float bias = b2[tc * 64 + f];

    float cnt_f = (float)max(g_ccnt[c], 1);
    float mean  = g_stats[tc * 128 + f] / cnt_f;
    float var   = g_stats[tc * 128 + 64 + f] / cnt_f - mean * mean;
    float inv   = rsqrtf(var + 1e-5f) * g1[tc * 64 + f];
    float beta  = be1[tc * 64 + f];

    int lo = g_coff[c], hi = g_coff[c + 1];
    int cnt = hi - lo;
    int per = gridDim.x * 4;
    int base = blockIdx.x * 4 + sub;

    for (int pos = base; pos < cnt; pos += per) {
        int node = g_clist[lo + pos];
        float v = g_h[node * 64 + f];
        v = fmaxf((v - mean) * inv + beta, 0.f);
        hsh[sub][f] = v;
        bar64(sub + 1);
        float o = bias;
#pragma unroll
        for (int i = 0; i < 64; ++i) o += hsh[sub][i] * wcol[i];
        g_x[node * 64 + f] = o;
        bar64(sub + 1);
    }
}

// ---------------------------------------------------------------------------
// Pooling: 512 threads/block, 8 rows in flight per column, shared reduce.
// ---------------------------------------------------------------------------
__global__ void pool_kernel(const void* __restrict__ batch, int t) {
    __shared__ int lohi[2];
    __shared__ float psh[8][64];
    int is64 = g_is64;
    int g = blockIdx.x;
    int tid = threadIdx.x;
    int r8 = tid >> 6;
    int f  = tid & 63;
    if (tid < 2) {
        int target = g + tid;
        int lo = 0, hi = NN;
        while (lo < hi) {
            int m = (lo + hi) >> 1;
            if (load_idx(batch, m, is64) < target) lo = m + 1; else hi = m;
        }
        lohi[tid] = lo;
    }
    __syncthreads();
    int lo = lohi[0], hi = lohi[1];
    float s0 = 0.f, s1 = 0.f;
    int r = lo + r8;
    for (; r + 16 <= hi; r += 16) {
        s0 += g_x[r * 64 + f];
        s1 += g_x[(r + 8) * 64 + f];
    }
    for (; r < hi; r += 8) s0 += g_x[r * 64 + f];
    psh[r8][f] = s0 + s1;
    __syncthreads();
    for (int s = 4; s > 0; s >>= 1) {
        if (r8 < s) psh[r8][f] += psh[r8 + s][f];
        __syncthreads();
    }
    if (r8 == 0) g_z[g * (HH * LL) + t * 64 + f] = psh[0][f];
}

// ---------------------------------------------------------------------------
// Head: 512 threads; Wp1 staged in shared.
// ---------------------------------------------------------------------------
__global__ void final_kernel(const float* __restrict__ Wp1, const float* __restrict__ bp1,
                             const float* __restrict__ gp,  const float* __restrict__ bep,
                             const float* __restrict__ Wp2, const float* __restrict__ bp2,
                             float* __restrict__ out) {
    __shared__ float Wsh[HH * LL * 64];   // 192*64 = 12288 floats = 48KB
    __shared__ float h1[GG * 64];
    __shared__ float msh[64], ish[64];
    int tid = threadIdx.x;
    const int NT = 512;

    for (int i = tid; i < HH * LL * 64; i += NT) Wsh[i] = Wp1[i];
    __syncthreads();

    for (int idx = tid; idx < GG * 64; idx += NT) {
        int g = idx >> 6, j = idx & 63;
        float s = bp1[j];
#pragma unroll 4
        for (int k = 0; k < HH * LL; ++k) s += g_z[g * (HH * LL) + k] * Wsh[k * 64 + j];
        h1[idx] = s;
    }
    __syncthreads();
    if (tid < 64) {
        float s = 0.f, q = 0.f;
        for (int g = 0; g < GG; ++g) { float v = h1[g * 64 + tid]; s += v; q += v * v; }
        float mean = s / (float)GG;
        float var  = q / (float)GG - mean * mean;
        msh[tid] = mean;
        ish[tid] = rsqrtf(var + 1e-5f) * gp[tid];
    }
    __syncthreads();
    for (int idx = tid; idx < GG * 64; idx += NT) {
        int j = idx & 63;
        h1[idx] = fmaxf((h1[idx] - msh[j]) * ish[j] + bep[j], 0.f);
    }
    // stage Wp2 into the front of Wsh (no longer needed)
    for (int i = tid; i < 64 * 64; i += NT) Wsh[i] = Wp2[i];
    __syncthreads();
    for (int idx = tid; idx < GG * 64; idx += NT) {
        int g = idx >> 6, j = idx & 63;
        float s = bp2[j];
#pragma unroll
        for (int k = 0; k < 64; ++k) s += h1[g * 64 + k] * Wsh[k * 64 + j];
        out[g * 64 + j] = s;
    }
}

// ---------------------------------------------------------------------------
extern "C" void kernel_launch(void* const* d_in, const int* in_sizes, int n_in,
                              void* d_out, int out_size) {
    const float* x     = (const float*)d_in[0];
    const int*   cl    = (const int*)d_in[1];
    const void*  eidx  = d_in[2];
    const void*  batch = d_in[3];
    const float* W1  = (const float*)d_in[4];
    const float* b1  = (const float*)d_in[5];
    const float* g1  = (const float*)d_in[6];
    const float* be1 = (const float*)d_in[7];
    const float* W2  = (const float*)d_in[8];
    const float* b2  = (const float*)d_in[9];
    const float* Wp1 = (const float*)d_in[10];
    const float* bp1 = (const float*)d_in[11];
    const float* gp  = (const float*)d_in[12];
    const float* bep = (const float*)d_in[13];
    const float* Wp2 = (const float*)d_in[14];
    const float* bp2 = (const float*)d_in[15];
    float* out = (float*)d_out;

    detect_kernel<<<1, 32>>>(eidx);
    init_kernel  <<<(NH + 255) / 256, 256>>>(x);
    count_kernel <<<(EE + NN + 255) / 256, 256>>>(eidx, cl);
    cscan_kernel <<<1, 32>>>();
    clist_kernel <<<(NN + 255) / 256, 256>>>(cl);
    blocksum_kernel <<<SCAN_BLK, 256>>>();
    scansmall_kernel<<<1, 256>>>();
    rowptr_kernel   <<<SCAN_BLK, 256>>>();
    fill_kernel  <<<(EE + 255) / 256, 256>>>(eidx);

    for (int t = 0; t < LL; ++t) {
        for (int c = 0; c < CC; ++c) {
            int tc = t * CC + c;
            gather_mm1_kernel<<<STEP_GRID, 256>>>(W1, b1, tc, c);
            bn_mm2_kernel    <<<STEP_GRID, 256>>>(g1, be1, W2, b2, tc, c);
        }
        pool_kernel<<<GG, 512>>>(batch, t);
    }
    final_kernel<<<1, 512>>>(Wp1, bp1, gp, bep, Wp2, bp2, out);
}

// round 6
// speedup vs baseline: 2.7313x; 1.1679x over previous
#include <cuda_runtime.h>

#define NN 50000
#define EE 800000
#define GG 64
#define HH 64
#define LL 3
#define CC 4
#define NH (NN*HH)
#define SCAN_BLK 200
#define STEP_GRID 296

// ---------------------------------------------------------------------------
// Scratch
// ---------------------------------------------------------------------------
__device__ float g_x[NH];
__device__ float g_h[NH];
__device__ int   g_rowptr[NN+1];
__device__ int   g_cursor[NN];
__device__ int   g_deg[NN];
__device__ int   g_csrc[EE];
__device__ float g_stats[LL*CC*128];
__device__ float g_z[GG*HH*LL];
__device__ int   g_ccnt[CC];
__device__ int   g_coff[CC+1];
__device__ int   g_ccur[CC];
__device__ int   g_clist[NN];
__device__ int   g_bsum[SCAN_BLK];
__device__ int   g_boff[SCAN_BLK];
__device__ int   g_is64;
__device__ unsigned int g_tick1;
__device__ unsigned int g_tick2;

__device__ __forceinline__ int load_idx(const void* p, long long i, int is64) {
    if (is64) return (int)((const long long*)p)[i];
    return ((const int*)p)[i];
}

__device__ __forceinline__ void bar64(int id) {
    asm volatile("bar.sync %0, 64;" :: "r"(id) : "memory");
}

// ---------------------------------------------------------------------------
// k0: init + dtype detect (block 0 thread 0)
// ---------------------------------------------------------------------------
__global__ void init_detect_kernel(const float* __restrict__ x, const void* eidx) {
    int idx = blockIdx.x * blockDim.x + threadIdx.x;
    if (idx < NH)         g_x[idx] = x[idx];
    if (idx < NN)         g_deg[idx] = 0;
    if (idx < LL*CC*128)  g_stats[idx] = 0.f;
    if (idx < CC)         g_ccnt[idx] = 0;
    if (idx == 0) { g_tick1 = 0; g_tick2 = 0; }
    if (blockIdx.x == 0 && threadIdx.x == 0) {
        const int* e32 = (const int*)eidx;
        int all0 = 1;
        for (int k = 0; k < 1024; ++k)
            if (e32[2 * k + 1] != 0) { all0 = 0; break; }
        g_is64 = all0;
    }
}

// ---------------------------------------------------------------------------
// k1: degree count + cluster count; last block computes cluster offsets
// ---------------------------------------------------------------------------
__global__ void count_cscan_kernel(const void* __restrict__ eidx,
                                   const int* __restrict__ cl) {
    int is64 = g_is64;
    int i = blockIdx.x * blockDim.x + threadIdx.x;
    if (i < EE) {
        int d = load_idx(eidx, (long long)EE + i, is64);
        atomicAdd(&g_deg[d], 1);
    } else if (i < EE + NN) {
        atomicAdd(&g_ccnt[cl[i - EE]], 1);
    }
    __threadfence();
    __syncthreads();
    if (threadIdx.x == 0) {
        unsigned int old = atomicAdd(&g_tick1, 1u);
        if (old == gridDim.x - 1) {
            int acc = 0;
            for (int c = 0; c < CC; ++c) {
                g_coff[c] = acc; g_ccur[c] = acc; acc += g_ccnt[c];
            }
            g_coff[CC] = acc;
        }
    }
}

// ---------------------------------------------------------------------------
// k2: cluster list fill + per-block degree sums; last block scans block sums
// ---------------------------------------------------------------------------
__global__ void clist_bsum_kernel(const int* __restrict__ cl) {
    __shared__ int sh[256];
    int b = blockIdx.x, tid = threadIdx.x;
    int idx = b * 256 + tid;
    int d = 0;
    if (idx < NN) {
        int pos = atomicAdd(&g_ccur[cl[idx]], 1);
        g_clist[pos] = idx;
        d = g_deg[idx];
    }
    sh[tid] = d;
    __syncthreads();
    for (int s = 128; s > 0; s >>= 1) {
        if (tid < s) sh[tid] += sh[tid + s];
        __syncthreads();
    }
    if (tid == 0) g_bsum[b] = sh[0];
    __threadfence();
    __syncthreads();
    if (tid == 0) {
        unsigned int old = atomicAdd(&g_tick2, 1u);
        if (old == gridDim.x - 1) {
            int acc = 0;
            for (int i = 0; i < SCAN_BLK; ++i) { int t = g_bsum[i]; g_boff[i] = acc; acc += t; }
            g_rowptr[NN] = acc;
        }
    }
}

// ---------------------------------------------------------------------------
// k3: per-block scan -> rowptr / cursor
// ---------------------------------------------------------------------------
__global__ void rowptr_kernel() {
    __shared__ int sh[256];
    int b = blockIdx.x, tid = threadIdx.x;
    int idx = b * 256 + tid;
    int v = (idx < NN) ? g_deg[idx] : 0;
    sh[tid] = v;
    __syncthreads();
    for (int s = 1; s < 256; s <<= 1) {
        int t = (tid >= s) ? sh[tid - s] : 0;
        __syncthreads();
        sh[tid] += t;
        __syncthreads();
    }
    if (idx < NN) {
        int excl = g_boff[b] + sh[tid] - v;
        g_rowptr[idx] = excl;
        g_cursor[idx] = excl;
    }
}

// k4: fill CSR
__global__ void fill_kernel(const void* __restrict__ eidx) {
    int is64 = g_is64;
    int i = blockIdx.x * blockDim.x + threadIdx.x;
    if (i < EE) {
        int s = load_idx(eidx, i, is64);
        int d = load_idx(eidx, (long long)EE + i, is64);
        int pos = atomicAdd(&g_cursor[d], 1);
        g_csrc[pos] = s;
    }
}

// ---------------------------------------------------------------------------
// Step kernel 1 (launch #5 on first step -> profiled by ncu):
// h = (agg + x) @ W1 + b1 over cluster-c nodes; BN stat accumulation.
// 4 groups of 64 threads; software-pipelined node processing.
// ---------------------------------------------------------------------------
__global__ void __launch_bounds__(256) gather_mm1_kernel(
        const float* __restrict__ W1, const float* __restrict__ b1,
        int tc, int c) {
    __shared__ float Wsh[4096];
    __shared__ float hsh[4][64];
    __shared__ int   esh[4][2][64];
    __shared__ float s1sh[64], s2sh[64];
    int tid = threadIdx.x;
    int sub = tid >> 6;
    int f   = tid & 63;
    int bid = sub + 1;

    const float* W = W1 + tc * 4096;
    for (int i = tid; i < 4096; i += 256) Wsh[i] = W[i];
    if (tid < 64) { s1sh[tid] = 0.f; s2sh[tid] = 0.f; }
    __syncthreads();

    float wcol[64];
#pragma unroll
    for (int i = 0; i < 64; ++i) wcol[i] = Wsh[i * 64 + f];
    float bias = b1[tc * 64 + f];

    int lo  = g_coff[c];
    int cnt = g_coff[c + 1] - lo;
    int per = gridDim.x * 4;
    int pos = blockIdx.x * 4 + sub;

    float a1 = 0.f, a2 = 0.f;
    int buf = 0;
    int node = 0, e0 = 0, deg = 0;
    float xv = 0.f;
    if (pos < cnt) {
        node = g_clist[lo + pos];
        e0   = g_rowptr[node];
        deg  = g_rowptr[node + 1] - e0;
        xv   = g_x[node * 64 + f];
        if (deg <= 64 && f < deg) esh[sub][0][f] = g_csrc[e0 + f];
    }
    bar64(bid);

    for (; pos < cnt; pos += per) {
        float acc0 = xv, acc1 = 0.f, acc2 = 0.f, acc3 = 0.f;
        float acc4 = 0.f, acc5 = 0.f, acc6 = 0.f, acc7 = 0.f;
        if (deg <= 64) {
            const int* ep = esh[sub][buf];
            int i = 0;
            for (; i + 8 <= deg; i += 8) {
                int s0 = ep[i+0], s1 = ep[i+1], s2 = ep[i+2], s3 = ep[i+3];
                int s4 = ep[i+4], s5 = ep[i+5], s6 = ep[i+6], s7 = ep[i+7];
                acc0 += g_x[s0 * 64 + f];
                acc1 += g_x[s1 * 64 + f];
                acc2 += g_x[s2 * 64 + f];
                acc3 += g_x[s3 * 64 + f];
                acc4 += g_x[s4 * 64 + f];
                acc5 += g_x[s5 * 64 + f];
                acc6 += g_x[s6 * 64 + f];
                acc7 += g_x[s7 * 64 + f];
            }
            for (; i < deg; ++i) acc0 += g_x[ep[i] * 64 + f];
        } else {
            // rare: degree > 64 -> chunked staging
            for (int chunk = e0; chunk < e0 + deg; chunk += 64) {
                int m = min(64, e0 + deg - chunk);
                if (f < m) esh[sub][buf][f] = g_csrc[chunk + f];
                bar64(bid);
                const int* ep = esh[sub][buf];
                int i = 0;
                for (; i + 8 <= m; i += 8) {
                    int s0 = ep[i+0], s1 = ep[i+1], s2 = ep[i+2], s3 = ep[i+3];
                    int s4 = ep[i+4], s5 = ep[i+5], s6 = ep[i+6], s7 = ep[i+7];
                    acc0 += g_x[s0 * 64 + f];
                    acc1 += g_x[s1 * 64 + f];
                    acc2 += g_x[s2 * 64 + f];
                    acc3 += g_x[s3 * 64 + f];
                    acc4 += g_x[s4 * 64 + f];
                    acc5 += g_x[s5 * 64 + f];
                    acc6 += g_x[s6 * 64 + f];
                    acc7 += g_x[s7 * 64 + f];
                }
                for (; i < m; ++i) acc0 += g_x[ep[i] * 64 + f];
                bar64(bid);
            }
        }
        hsh[sub][f] = ((acc0 + acc1) + (acc2 + acc3)) + ((acc4 + acc5) + (acc6 + acc7));

        // prestage next node (overlaps with mm below)
        int npos = pos + per;
        int nnode = 0, ne0 = 0, ndeg = 0;
        float nxv = 0.f;
        if (npos < cnt) {
            nnode = g_clist[lo + npos];
            ne0   = g_rowptr[nnode];
            ndeg  = g_rowptr[nnode + 1] - ne0;
            nxv   = g_x[nnode * 64 + f];
            if (ndeg <= 64 && f < ndeg) esh[sub][buf ^ 1][f] = g_csrc[ne0 + f];
        }
        bar64(bid);
        float o = bias;
#pragma unroll
        for (int i = 0; i < 64; ++i) o += hsh[sub][i] * wcol[i];
        g_h[node * 64 + f] = o;
        a1 += o; a2 += o * o;
        bar64(bid);

        node = nnode; e0 = ne0; deg = ndeg; xv = nxv; buf ^= 1;
    }
    atomicAdd(&s1sh[f], a1);
    atomicAdd(&s2sh[f], a2);
    __syncthreads();
    if (tid < 64) {
        atomicAdd(&g_stats[tc * 128 + tid],      s1sh[tid]);
        atomicAdd(&g_stats[tc * 128 + 64 + tid], s2sh[tid]);
    }
}

// ---------------------------------------------------------------------------
// Step kernel 2: BN + ReLU + @W2 + b2 -> write back masked rows (pipelined)
// ---------------------------------------------------------------------------
__global__ void __launch_bounds__(256) bn_mm2_kernel(
        const float* __restrict__ g1, const float* __restrict__ be1,
        const float* __restrict__ W2, const float* __restrict__ b2,
        int tc, int c) {
    __shared__ float Wsh[4096];
    __shared__ float hsh[4][64];
    int tid = threadIdx.x;
    int sub = tid >> 6;
    int f   = tid & 63;
    int bid = sub + 1;

    const float* W = W2 + tc * 4096;
    for (int i = tid; i < 4096; i += 256) Wsh[i] = W[i];
    __syncthreads();

    float wcol[64];
#pragma unroll
    for (int i = 0; i < 64; ++i) wcol[i] = Wsh[i * 64 + f];
    float bias = b2[tc * 64 + f];

    float cnt_f = (float)max(g_ccnt[c], 1);
    float mean  = g_stats[tc * 128 + f] / cnt_f;
    float var   = g_stats[tc * 128 + 64 + f] / cnt_f - mean * mean;
    float inv   = rsqrtf(var + 1e-5f) * g1[tc * 64 + f];
    float beta  = be1[tc * 64 + f];

    int lo  = g_coff[c];
    int cnt = g_coff[c + 1] - lo;
    int per = gridDim.x * 4;
    int pos = blockIdx.x * 4 + sub;

    int node = 0;
    float hv = 0.f;
    if (pos < cnt) {
        node = g_clist[lo + pos];
        hv   = g_h[node * 64 + f];
    }
    for (; pos < cnt; pos += per) {
        hsh[sub][f] = fmaxf((hv - mean) * inv + beta, 0.f);
        // prefetch next
        int npos = pos + per;
        int nnode = 0;
        float nhv = 0.f;
        if (npos < cnt) {
            nnode = g_clist[lo + npos];
            nhv   = g_h[nnode * 64 + f];
        }
        bar64(bid);
        float o = bias;
#pragma unroll
        for (int i = 0; i < 64; ++i) o += hsh[sub][i] * wcol[i];
        g_x[node * 64 + f] = o;
        bar64(bid);
        node = nnode; hv = nhv;
    }
}

// ---------------------------------------------------------------------------
// Pooling: 1024 threads/block, 16 row-groups x 2-deep, shared reduce.
// ---------------------------------------------------------------------------
__global__ void pool_kernel(const void* __restrict__ batch, int t) {
    __shared__ int lohi[2];
    __shared__ float psh[16][64];
    int is64 = g_is64;
    int g = blockIdx.x;
    int tid = threadIdx.x;
    int rg = tid >> 6;          // 0..15
    int f  = tid & 63;
    if (tid < 2) {
        int target = g + tid;
        int lo = 0, hi = NN;
        while (lo < hi) {
            int m = (lo + hi) >> 1;
            if (load_idx(batch, m, is64) < target) lo = m + 1; else hi = m;
        }
        lohi[tid] = lo;
    }
    __syncthreads();
    int lo = lohi[0], hi = lohi[1];
    float s0 = 0.f, s1 = 0.f;
    int r = lo + rg;
    for (; r + 32 <= hi; r += 32) {
        s0 += g_x[r * 64 + f];
        s1 += g_x[(r + 16) * 64 + f];
    }
    for (; r < hi; r += 16) s0 += g_x[r * 64 + f];
    psh[rg][f] = s0 + s1;
    __syncthreads();
    for (int s = 8; s > 0; s >>= 1) {
        if (rg < s) psh[rg][f] += psh[rg + s][f];
        __syncthreads();
    }
    if (rg == 0) g_z[g * (HH * LL) + t * 64 + f] = psh[0][f];
}

// ---------------------------------------------------------------------------
// Head
// ---------------------------------------------------------------------------
__global__ void final_kernel(const float* __restrict__ Wp1, const float* __restrict__ bp1,
                             const float* __restrict__ gp,  const float* __restrict__ bep,
                             const float* __restrict__ Wp2, const float* __restrict__ bp2,
                             float* __restrict__ out) {
    __shared__ float Wsh[HH * LL * 64];
    __shared__ float h1[GG * 64];
    __shared__ float msh[64], ish[64];
    int tid = threadIdx.x;
    const int NT = 512;

    for (int i = tid; i < HH * LL * 64; i += NT) Wsh[i] = Wp1[i];
    __syncthreads();

    for (int idx = tid; idx < GG * 64; idx += NT) {
        int g = idx >> 6, j = idx & 63;
        float s = bp1[j];
#pragma unroll 4
        for (int k = 0; k < HH * LL; ++k) s += g_z[g * (HH * LL) + k] * Wsh[k * 64 + j];
        h1[idx] = s;
    }
    __syncthreads();
    if (tid < 64) {
        float s = 0.f, q = 0.f;
        for (int g = 0; g < GG; ++g) { float v = h1[g * 64 + tid]; s += v; q += v * v; }
        float mean = s / (float)GG;
        float var  = q / (float)GG - mean * mean;
        msh[tid] = mean;
        ish[tid] = rsqrtf(var + 1e-5f) * gp[tid];
    }
    __syncthreads();
    for (int idx = tid; idx < GG * 64; idx += NT) {
        int j = idx & 63;
        h1[idx] = fmaxf((h1[idx] - msh[j]) * ish[j] + bep[j], 0.f);
    }
    for (int i = tid; i < 64 * 64; i += NT) Wsh[i] = Wp2[i];
    __syncthreads();
    for (int idx = tid; idx < GG * 64; idx += NT) {
        int g = idx >> 6, j = idx & 63;
        float s = bp2[j];
#pragma unroll
        for (int k = 0; k < 64; ++k) s += h1[g * 64 + k] * Wsh[k * 64 + j];
        out[g * 64 + j] = s;
    }
}

// ---------------------------------------------------------------------------
extern "C" void kernel_launch(void* const* d_in, const int* in_sizes, int n_in,
                              void* d_out, int out_size) {
    const float* x     = (const float*)d_in[0];
    const int*   cl    = (const int*)d_in[1];
    const void*  eidx  = d_in[2];
    const void*  batch = d_in[3];
    const float* W1  = (const float*)d_in[4];
    const float* b1  = (const float*)d_in[5];
    const float* g1  = (const float*)d_in[6];
    const float* be1 = (const float*)d_in[7];
    const float* W2  = (const float*)d_in[8];
    const float* b2  = (const float*)d_in[9];
    const float* Wp1 = (const float*)d_in[10];
    const float* bp1 = (const float*)d_in[11];
    const float* gp  = (const float*)d_in[12];
    const float* bep = (const float*)d_in[13];
    const float* Wp2 = (const float*)d_in[14];
    const float* bp2 = (const float*)d_in[15];
    float* out = (float*)d_out;

    init_detect_kernel<<<(NH + 255) / 256, 256>>>(x, eidx);          // launch 0
    count_cscan_kernel<<<(EE + NN + 255) / 256, 256>>>(eidx, cl);    // launch 1
    clist_bsum_kernel <<<SCAN_BLK, 256>>>(cl);                       // launch 2
    rowptr_kernel     <<<SCAN_BLK, 256>>>();                         // launch 3
    fill_kernel       <<<(EE + 255) / 256, 256>>>(eidx);             // launch 4

    for (int t = 0; t < LL; ++t) {
        for (int c = 0; c < CC; ++c) {
            int tc = t * CC + c;
            gather_mm1_kernel<<<STEP_GRID, 256>>>(W1, b1, tc, c);    // first: launch 5 (profiled)
            bn_mm2_kernel    <<<STEP_GRID, 256>>>(g1, be1, W2, b2, tc, c);
        }
        pool_kernel<<<GG, 1024>>>(batch, t);
    }
    final_kernel<<<1, 512>>>(Wp1, bp1, gp, bep, Wp2, bp2, out);
}

// round 8
// speedup vs baseline: 3.1022x; 1.1358x over previous
#include <cuda_runtime.h>

#define NN 50000
#define EE 800000
#define GG 64
#define HH 64
#define LL 3
#define CC 4
#define NH (NN*HH)
#define NB 296                 // 2 blocks/SM x 148 SMs, all co-resident
#define NT 256
#define NODE_CHUNK 169         // ceil(NN/NB)

// ---------------------------------------------------------------------------
// Scratch
// ---------------------------------------------------------------------------
__device__ __align__(16) float g_x[NH];
__device__ __align__(16) float g_h[NH];
__device__ int   g_rowptr[NN+1];
__device__ int   g_cursor[NN];
__device__ int   g_deg[NN];
__device__ int   g_csrc[EE];
__device__ float g_stats[LL*CC*128];
__device__ float g_z[GG*HH*LL];
__device__ int   g_ccnt[CC];
__device__ int   g_coff[CC+1];
__device__ int   g_ccur[CC];
__device__ int   g_clist[NN];
__device__ int   g_bsum[NB];
__device__ int   g_boff[NB];
__device__ int   g_is64;
__device__ unsigned int g_bar_arrive;   // zero-init; self-resetting
__device__ unsigned int g_bar_gen;      // monotonically increasing across replays

__device__ __forceinline__ int load_idx(const void* p, long long i, int is64) {
    if (is64) return (int)((const long long*)p)[i];
    return ((const int*)p)[i];
}

__device__ __forceinline__ void bar64(int id) {
    asm volatile("bar.sync %0, 64;" :: "r"(id) : "memory");
}

// Software grid barrier: all NB blocks must be resident (guaranteed by
// launch_bounds(256,2) + 35KB smem on a 148-SM chip with grid=296).
__device__ __forceinline__ void grid_barrier() {
    __syncthreads();
    if (threadIdx.x == 0) {
        __threadfence();
        volatile unsigned int* genp = &g_bar_gen;
        unsigned int gen = *genp;
        if (atomicAdd(&g_bar_arrive, 1u) == NB - 1) {
            g_bar_arrive = 0;
            __threadfence();
            *genp = gen + 1;
        } else {
            while (*genp == gen) __nanosleep(32);
        }
    }
    __syncthreads();
}

// ---------------------------------------------------------------------------
// Persistent kernel: everything except the tiny head
// ---------------------------------------------------------------------------
__global__ void __launch_bounds__(NT, 2) persistent_kernel(
        const float* __restrict__ x, const int* __restrict__ cl,
        const void* __restrict__ eidx, const void* __restrict__ batch,
        const float* __restrict__ W1, const float* __restrict__ b1,
        const float* __restrict__ g1, const float* __restrict__ be1,
        const float* __restrict__ W2, const float* __restrict__ b2) {
    __shared__ float Wsh1[4096];
    __shared__ float Wsh2[4096];
    __shared__ float hsh[4][64];
    __shared__ int   esh[4][2][64];     // also reused as int sh[512] in scans
    __shared__ float s1sh[64], s2sh[64];

    const int tid = threadIdx.x;
    const int b   = blockIdx.x;
    const int gtid = b * NT + tid;
    const int gstride = NB * NT;
    const int sub = tid >> 6;
    const int f   = tid & 63;
    const int bid = sub + 1;

    // ---- P0: init + dtype detect ----
    for (int i = gtid; i < NH / 4; i += gstride)
        ((float4*)g_x)[i] = ((const float4*)x)[i];
    for (int i = gtid; i < NN; i += gstride) g_deg[i] = 0;
    for (int i = gtid; i < LL*CC*128; i += gstride) g_stats[i] = 0.f;
    if (gtid < CC) g_ccnt[gtid] = 0;
    if (b == 0) {
        const int* e32 = (const int*)eidx;
        int bad = 0;
        for (int k = tid; k < 1024; k += NT) if (e32[2 * k + 1] != 0) bad = 1;
        int* sh = (int*)esh;
        sh[tid] = bad;
        __syncthreads();
        for (int s = 128; s > 0; s >>= 1) {
            if (tid < s) sh[tid] |= sh[tid + s];
            __syncthreads();
        }
        if (tid == 0) g_is64 = !sh[0];
    }
    grid_barrier();
    const int is64 = g_is64;

    // ---- P1: degree + cluster count ----
    for (int i = gtid; i < EE; i += gstride) {
        int d = load_idx(eidx, (long long)EE + i, is64);
        atomicAdd(&g_deg[d], 1);
    }
    for (int i = gtid; i < NN; i += gstride) atomicAdd(&g_ccnt[cl[i]], 1);
    grid_barrier();

    // ---- P2: cluster offsets (block0) + local inclusive degree scans ----
    if (b == 0 && tid == 0) {
        int acc = 0;
        for (int c = 0; c < CC; ++c) { g_coff[c] = acc; g_ccur[c] = acc; acc += g_ccnt[c]; }
        g_coff[CC] = acc;
    }
    {
        int* sh = (int*)esh;
        int idx = b * NODE_CHUNK + tid;
        int v = (tid < NODE_CHUNK && idx < NN) ? g_deg[idx] : 0;
        sh[tid] = v;
        __syncthreads();
        for (int s = 1; s < NT; s <<= 1) {
            int tv = (tid >= s) ? sh[tid - s] : 0;
            __syncthreads();
            sh[tid] += tv;
            __syncthreads();
        }
        if (tid < NODE_CHUNK && idx < NN) g_rowptr[idx] = sh[tid];  // local inclusive
        if (tid == NT - 1) g_bsum[b] = sh[NT - 1];
    }
    grid_barrier();

    // ---- P3: scan block sums (block0); fill cluster lists (all) ----
    if (b == 0 && tid == 0) {
        int acc = 0;
        for (int i = 0; i < NB; ++i) { int t = g_bsum[i]; g_boff[i] = acc; acc += t; }
        g_rowptr[NN] = acc;
    }
    for (int i = gtid; i < NN; i += gstride) {
        int pos = atomicAdd(&g_ccur[cl[i]], 1);
        g_clist[pos] = i;
    }
    grid_barrier();

    // ---- P4: finalize rowptr/cursor ----
    {
        int idx = b * NODE_CHUNK + tid;
        if (tid < NODE_CHUNK && idx < NN) {
            int excl = g_boff[b] + g_rowptr[idx] - g_deg[idx];
            g_rowptr[idx] = excl;
            g_cursor[idx] = excl;
        }
    }
    grid_barrier();

    // ---- P5: CSR fill ----
    for (int i = gtid; i < EE; i += gstride) {
        int s = load_idx(eidx, i, is64);
        int d = load_idx(eidx, (long long)EE + i, is64);
        int pos = atomicAdd(&g_cursor[d], 1);
        g_csrc[pos] = s;
    }
    grid_barrier();

    // ---- main loop: 3 layers x 4 clusters ----
    float wcol[64];
    for (int t = 0; t < LL; ++t) {
        for (int c = 0; c < CC; ++c) {
            const int tc = t * CC + c;
            // stage both weight matrices for this step
            for (int i = tid; i < 4096; i += NT) {
                Wsh1[i] = W1[tc * 4096 + i];
                Wsh2[i] = W2[tc * 4096 + i];
            }
            if (tid < 64) { s1sh[tid] = 0.f; s2sh[tid] = 0.f; }
            __syncthreads();

            // === phase A: gather + mm1 + stats ===
#pragma unroll
            for (int i = 0; i < 64; ++i) wcol[i] = Wsh1[i * 64 + f];
            float bias = b1[tc * 64 + f];

            const int lo  = g_coff[c];
            const int cnt = g_coff[c + 1] - lo;
            const int per = NB * 4;
            int pos = b * 4 + sub;

            float a1 = 0.f, a2 = 0.f;
            int buf = 0;
            int node = 0, e0 = 0, deg = 0;
            float xv = 0.f;
            if (pos < cnt) {
                node = g_clist[lo + pos];
                e0   = g_rowptr[node];
                deg  = g_rowptr[node + 1] - e0;
                xv   = g_x[node * 64 + f];
                if (deg <= 64 && f < deg) esh[sub][0][f] = g_csrc[e0 + f];
            }
            bar64(bid);

            for (; pos < cnt; pos += per) {
                float acc0 = xv, acc1 = 0.f, acc2 = 0.f, acc3 = 0.f;
                float acc4 = 0.f, acc5 = 0.f, acc6 = 0.f, acc7 = 0.f;
                if (deg <= 64) {
                    const int* ep = esh[sub][buf];
                    int i = 0;
                    for (; i + 8 <= deg; i += 8) {
                        int s0 = ep[i+0], s1 = ep[i+1], s2 = ep[i+2], s3 = ep[i+3];
                        int s4 = ep[i+4], s5 = ep[i+5], s6 = ep[i+6], s7 = ep[i+7];
                        acc0 += g_x[s0 * 64 + f];
                        acc1 += g_x[s1 * 64 + f];
                        acc2 += g_x[s2 * 64 + f];
                        acc3 += g_x[s3 * 64 + f];
                        acc4 += g_x[s4 * 64 + f];
                        acc5 += g_x[s5 * 64 + f];
                        acc6 += g_x[s6 * 64 + f];
                        acc7 += g_x[s7 * 64 + f];
                    }
                    for (; i < deg; ++i) acc0 += g_x[ep[i] * 64 + f];
                } else {
                    for (int chunk = e0; chunk < e0 + deg; chunk += 64) {
                        int m = min(64, e0 + deg - chunk);
                        if (f < m) esh[sub][buf][f] = g_csrc[chunk + f];
                        bar64(bid);
                        const int* ep = esh[sub][buf];
                        int i = 0;
                        for (; i + 8 <= m; i += 8) {
                            int s0 = ep[i+0], s1 = ep[i+1], s2 = ep[i+2], s3 = ep[i+3];
                            int s4 = ep[i+4], s5 = ep[i+5], s6 = ep[i+6], s7 = ep[i+7];
                            acc0 += g_x[s0 * 64 + f];
                            acc1 += g_x[s1 * 64 + f];
                            acc2 += g_x[s2 * 64 + f];
                            acc3 += g_x[s3 * 64 + f];
                            acc4 += g_x[s4 * 64 + f];
                            acc5 += g_x[s5 * 64 + f];
                            acc6 += g_x[s6 * 64 + f];
                            acc7 += g_x[s7 * 64 + f];
                        }
                        for (; i < m; ++i) acc0 += g_x[ep[i] * 64 + f];
                        bar64(bid);
                    }
                }
                hsh[sub][f] = ((acc0 + acc1) + (acc2 + acc3)) + ((acc4 + acc5) + (acc6 + acc7));

                // prestage next node while the group does the inner product
                int npos = pos + per;
                int nnode = 0, ne0 = 0, ndeg = 0;
                float nxv = 0.f;
                if (npos < cnt) {
                    nnode = g_clist[lo + npos];
                    ne0   = g_rowptr[nnode];
                    ndeg  = g_rowptr[nnode + 1] - ne0;
                    nxv   = g_x[nnode * 64 + f];
                    if (ndeg <= 64 && f < ndeg) esh[sub][buf ^ 1][f] = g_csrc[ne0 + f];
                }
                bar64(bid);
                float o0 = 0.f, o1 = 0.f, o2 = 0.f, o3 = 0.f;
#pragma unroll
                for (int i = 0; i < 16; ++i) {
                    o0 += hsh[sub][i]      * wcol[i];
                    o1 += hsh[sub][i + 16] * wcol[i + 16];
                    o2 += hsh[sub][i + 32] * wcol[i + 32];
                    o3 += hsh[sub][i + 48] * wcol[i + 48];
                }
                float o = bias + ((o0 + o1) + (o2 + o3));
                g_h[node * 64 + f] = o;
                a1 += o; a2 += o * o;
                bar64(bid);

                node = nnode; e0 = ne0; deg = ndeg; xv = nxv; buf ^= 1;
            }
            atomicAdd(&s1sh[f], a1);
            atomicAdd(&s2sh[f], a2);
            __syncthreads();
            if (tid < 64) {
                atomicAdd(&g_stats[tc * 128 + tid],      s1sh[tid]);
                atomicAdd(&g_stats[tc * 128 + 64 + tid], s2sh[tid]);
            }
            grid_barrier();

            // === phase B: BN + ReLU + mm2, write back x ===
#pragma unroll
            for (int i = 0; i < 64; ++i) wcol[i] = Wsh2[i * 64 + f];
            float bias2 = b2[tc * 64 + f];
            float cnt_f = (float)max(cnt, 1);
            float mean  = g_stats[tc * 128 + f] / cnt_f;
            float var   = g_stats[tc * 128 + 64 + f] / cnt_f - mean * mean;
            float inv   = rsqrtf(var + 1e-5f) * g1[tc * 64 + f];
            float beta  = be1[tc * 64 + f];

            pos = b * 4 + sub;
            int node2 = 0;
            float hv = 0.f;
            if (pos < cnt) {
                node2 = g_clist[lo + pos];
                hv    = g_h[node2 * 64 + f];
            }
            for (; pos < cnt; pos += per) {
                hsh[sub][f] = fmaxf((hv - mean) * inv + beta, 0.f);
                int npos = pos + per;
                int nnode = 0;
                float nhv = 0.f;
                if (npos < cnt) {
                    nnode = g_clist[lo + npos];
                    nhv   = g_h[nnode * 64 + f];
                }
                bar64(bid);
                float o0 = 0.f, o1 = 0.f, o2 = 0.f, o3 = 0.f;
#pragma unroll
                for (int i = 0; i < 16; ++i) {
                    o0 += hsh[sub][i]      * wcol[i];
                    o1 += hsh[sub][i + 16] * wcol[i + 16];
                    o2 += hsh[sub][i + 32] * wcol[i + 32];
                    o3 += hsh[sub][i + 48] * wcol[i + 48];
                }
                g_x[node2 * 64 + f] = bias2 + ((o0 + o1) + (o2 + o3));
                bar64(bid);
                node2 = nnode; hv = nhv;
            }
            grid_barrier();
        }

        // ---- pooling for layer t: blocks 0..63, one graph each ----
        if (b < GG) {
            int* lohi = (int*)esh;
            if (tid < 2) {
                int target = b + tid;
                int lo2 = 0, hi2 = NN;
                while (lo2 < hi2) {
                    int m = (lo2 + hi2) >> 1;
                    if (load_idx(batch, m, is64) < target) lo2 = m + 1; else hi2 = m;
                }
                lohi[tid] = lo2;
            }
            __syncthreads();
            int lo2 = lohi[0], hi2 = lohi[1];
            float s0 = 0.f, s1 = 0.f;
            int r = lo2 + sub;
            for (; r + 8 <= hi2; r += 8) {
                s0 += g_x[r * 64 + f];
                s1 += g_x[(r + 4) * 64 + f];
            }
            for (; r < hi2; r += 4) s0 += g_x[r * 64 + f];
            hsh[sub][f] = s0 + s1;
            __syncthreads();
            if (sub == 0) {
                float v = hsh[0][f] + hsh[1][f] + hsh[2][f] + hsh[3][f];
                g_z[b * (HH * LL) + t * 64 + f] = v;
            }
        }
        grid_barrier();
    }
}

// ---------------------------------------------------------------------------
// Head: z[64,192] @ Wp1 -> BN -> ReLU -> @ Wp2 -> out
// ---------------------------------------------------------------------------
__global__ void final_kernel(const float* __restrict__ Wp1, const float* __restrict__ bp1,
                             const float* __restrict__ gp,  const float* __restrict__ bep,
                             const float* __restrict__ Wp2, const float* __restrict__ bp2,
                             float* __restrict__ out) {
    __shared__ float Wsh[HH * LL * 64];
    __shared__ float h1[GG * 64];
    __shared__ float msh[64], ish[64];
    int tid = threadIdx.x;
    const int FT = 512;

    for (int i = tid; i < HH * LL * 64; i += FT) Wsh[i] = Wp1[i];
    __syncthreads();

    for (int idx = tid; idx < GG * 64; idx += FT) {
        int g = idx >> 6, j = idx & 63;
        float s = bp1[j];
#pragma unroll 4
        for (int k = 0; k < HH * LL; ++k) s += g_z[g * (HH * LL) + k] * Wsh[k * 64 + j];
        h1[idx] = s;
    }
    __syncthreads();
    if (tid < 64) {
        float s = 0.f, q = 0.f;
        for (int g = 0; g < GG; ++g) { float v = h1[g * 64 + tid]; s += v; q += v * v; }
        float mean = s / (float)GG;
        float var  = q / (float)GG - mean * mean;
        msh[tid] = mean;
        ish[tid] = rsqrtf(var + 1e-5f) * gp[tid];
    }
    __syncthreads();
    for (int idx = tid; idx < GG * 64; idx += FT) {
        int j = idx & 63;
        h1[idx] = fmaxf((h1[idx] - msh[j]) * ish[j] + bep[j], 0.f);
    }
    for (int i = tid; i < 64 * 64; i += FT) Wsh[i] = Wp2[i];
    __syncthreads();
    for (int idx = tid; idx < GG * 64; idx += FT) {
        int g = idx >> 6, j = idx & 63;
        float s = bp2[j];
#pragma unroll
        for (int k = 0; k < 64; ++k) s += h1[g * 64 + k] * Wsh[k * 64 + j];
        out[g * 64 + j] = s;
    }
}

// ---------------------------------------------------------------------------
extern "C" void kernel_launch(void* const* d_in, const int* in_sizes, int n_in,
                              void* d_out, int out_size) {
    const float* x     = (const float*)d_in[0];
    const int*   cl    = (const int*)d_in[1];
    const void*  eidx  = d_in[2];
    const void*  batch = d_in[3];
    const float* W1  = (const float*)d_in[4];
    const float* b1  = (const float*)d_in[5];
    const float* g1  = (const float*)d_in[6];
    const float* be1 = (const float*)d_in[7];
    const float* W2  = (const float*)d_in[8];
    const float* b2  = (const float*)d_in[9];
    const float* Wp1 = (const float*)d_in[10];
    const float* bp1 = (const float*)d_in[11];
    const float* gp  = (const float*)d_in[12];
    const float* bep = (const float*)d_in[13];
    const float* Wp2 = (const float*)d_in[14];
    const float* bp2 = (const float*)d_in[15];
    float* out = (float*)d_out;

    persistent_kernel<<<NB, NT>>>(x, cl, eidx, batch, W1, b1, g1, be1, W2, b2);
    final_kernel<<<1, 512>>>(Wp1, bp1, gp, bep, Wp2, bp2, out);
}

// round 9
// speedup vs baseline: 3.4109x; 1.0995x over previous
#include <cuda_runtime.h>

#define NN 50000
#define EE 800000
#define GG 64
#define HH 64
#define LL 3
#define CC 4
#define NH (NN*HH)
#define NB 296                 // 2 blocks/SM x 148 SMs, all co-resident
#define NT 256
#define NODE_CHUNK 169         // ceil(NN/NB)

// ---------------------------------------------------------------------------
// Scratch
// ---------------------------------------------------------------------------
__device__ __align__(16) float g_x[NH];
__device__ __align__(16) float g_h[NH];
__device__ int   g_rowptr[NN+1];
__device__ int   g_cursor[NN];
__device__ int   g_deg[NN];
__device__ int   g_csrc[EE];
__device__ float g_stats[LL*CC*128];
__device__ float g_z[GG*HH*LL];
__device__ float g_h1[GG*HH];       // head intermediate
__device__ float g_bnp[128];        // head BN mean/inv
__device__ int   g_ccnt[CC];
__device__ int   g_coff[CC+1];
__device__ int   g_ccur[CC];
__device__ int   g_clist[NN];
__device__ int   g_bsum[NB];
__device__ int   g_boff[NB];
__device__ int   g_is64;
__device__ unsigned int g_bar_arrive;   // zero-init; self-resetting
__device__ unsigned int g_bar_gen;      // monotonically increasing across replays

__device__ __forceinline__ int load_idx(const void* p, long long i, int is64) {
    if (is64) return (int)((const long long*)p)[i];
    return ((const int*)p)[i];
}

__device__ __forceinline__ void bar64(int id) {
    asm volatile("bar.sync %0, 64;" :: "r"(id) : "memory");
}

// Software grid barrier (all NB blocks co-resident by construction)
__device__ __forceinline__ void grid_barrier() {
    __syncthreads();
    if (threadIdx.x == 0) {
        __threadfence();
        volatile unsigned int* genp = &g_bar_gen;
        unsigned int gen = *genp;
        if (atomicAdd(&g_bar_arrive, 1u) == NB - 1) {
            g_bar_arrive = 0;
            __threadfence();
            *genp = gen + 1;
        } else {
            while (*genp == gen) __nanosleep(32);
        }
    }
    __syncthreads();
}

// ---------------------------------------------------------------------------
// Single persistent kernel: everything
// ---------------------------------------------------------------------------
__global__ void __launch_bounds__(NT, 2) persistent_kernel(
        const float* __restrict__ x, const int* __restrict__ cl,
        const void* __restrict__ eidx, const void* __restrict__ batch,
        const float* __restrict__ W1, const float* __restrict__ b1,
        const float* __restrict__ g1, const float* __restrict__ be1,
        const float* __restrict__ W2, const float* __restrict__ b2,
        const float* __restrict__ Wp1, const float* __restrict__ bp1,
        const float* __restrict__ gp,  const float* __restrict__ bep,
        const float* __restrict__ Wp2, const float* __restrict__ bp2,
        float* __restrict__ out) {
    __shared__ float Wsh1[4096];
    __shared__ float Wsh2[4096];
    __shared__ float hsh[4][64];
    __shared__ int   esh[4][2][64];     // reused as int sh[512] in scans
    __shared__ float s1sh[64], s2sh[64];

    const int tid = threadIdx.x;
    const int b   = blockIdx.x;
    const int gtid = b * NT + tid;
    const int gstride = NB * NT;
    const int sub = tid >> 6;
    const int f   = tid & 63;
    const int bid = sub + 1;

    // ---- P0: init + dtype detect ----
    for (int i = gtid; i < NH / 4; i += gstride)
        ((float4*)g_x)[i] = ((const float4*)x)[i];
    for (int i = gtid; i < NN; i += gstride) g_deg[i] = 0;
    for (int i = gtid; i < LL*CC*128; i += gstride) g_stats[i] = 0.f;
    for (int i = gtid; i < GG*HH*LL; i += gstride) g_z[i] = 0.f;
    if (gtid < CC) g_ccnt[gtid] = 0;
    if (b == 0) {
        const int* e32 = (const int*)eidx;
        int bad = 0;
        for (int k = tid; k < 1024; k += NT) if (e32[2 * k + 1] != 0) bad = 1;
        int* sh = (int*)esh;
        sh[tid] = bad;
        __syncthreads();
        for (int s = 128; s > 0; s >>= 1) {
            if (tid < s) sh[tid] |= sh[tid + s];
            __syncthreads();
        }
        if (tid == 0) g_is64 = !sh[0];
    }
    grid_barrier();
    const int is64 = g_is64;

    // ---- P1: degree + cluster count ----
    for (int i = gtid; i < EE; i += gstride) {
        int d = load_idx(eidx, (long long)EE + i, is64);
        atomicAdd(&g_deg[d], 1);
    }
    for (int i = gtid; i < NN; i += gstride) atomicAdd(&g_ccnt[cl[i]], 1);
    grid_barrier();

    // ---- P2: cluster offsets (block0) + local inclusive degree scans ----
    if (b == 0 && tid == 0) {
        int acc = 0;
        for (int c = 0; c < CC; ++c) { g_coff[c] = acc; g_ccur[c] = acc; acc += g_ccnt[c]; }
        g_coff[CC] = acc;
    }
    {
        int* sh = (int*)esh;
        int idx = b * NODE_CHUNK + tid;
        int v = (tid < NODE_CHUNK && idx < NN) ? g_deg[idx] : 0;
        sh[tid] = v;
        __syncthreads();
        for (int s = 1; s < NT; s <<= 1) {
            int tv = (tid >= s) ? sh[tid - s] : 0;
            __syncthreads();
            sh[tid] += tv;
            __syncthreads();
        }
        if (tid < NODE_CHUNK && idx < NN) g_rowptr[idx] = sh[tid];  // local inclusive
        if (tid == NT - 1) g_bsum[b] = sh[NT - 1];
    }
    grid_barrier();

    // ---- P3: scan block sums (block0); fill cluster lists (all) ----
    if (b == 0 && tid == 0) {
        int acc = 0;
        for (int i = 0; i < NB; ++i) { int t = g_bsum[i]; g_boff[i] = acc; acc += t; }
        g_rowptr[NN] = acc;
    }
    for (int i = gtid; i < NN; i += gstride) {
        int pos = atomicAdd(&g_ccur[cl[i]], 1);
        g_clist[pos] = i;
    }
    grid_barrier();

    // ---- P4: finalize rowptr/cursor ----
    {
        int idx = b * NODE_CHUNK + tid;
        if (tid < NODE_CHUNK && idx < NN) {
            int excl = g_boff[b] + g_rowptr[idx] - g_deg[idx];
            g_rowptr[idx] = excl;
            g_cursor[idx] = excl;
        }
    }
    grid_barrier();

    // ---- P5: CSR fill ----
    for (int i = gtid; i < EE; i += gstride) {
        int s = load_idx(eidx, i, is64);
        int d = load_idx(eidx, (long long)EE + i, is64);
        int pos = atomicAdd(&g_cursor[d], 1);
        g_csrc[pos] = s;
    }
    grid_barrier();

    // ---- main loop: 3 layers x 4 clusters ----
    float wcol[64];
    for (int t = 0; t < LL; ++t) {
        for (int c = 0; c < CC; ++c) {
            const int tc = t * CC + c;
            for (int i = tid; i < 4096; i += NT) {
                Wsh1[i] = W1[tc * 4096 + i];
                Wsh2[i] = W2[tc * 4096 + i];
            }
            if (tid < 64) { s1sh[tid] = 0.f; s2sh[tid] = 0.f; }
            __syncthreads();

            // === phase A: gather + mm1 + stats ===
#pragma unroll
            for (int i = 0; i < 64; ++i) wcol[i] = Wsh1[i * 64 + f];
            float bias = b1[tc * 64 + f];

            const int lo  = g_coff[c];
            const int cnt = g_coff[c + 1] - lo;
            const int per = NB * 4;
            int pos = b * 4 + sub;

            float a1 = 0.f, a2 = 0.f;
            int buf = 0;
            int node = 0, e0 = 0, deg = 0;
            float xv = 0.f;
            if (pos < cnt) {
                node = g_clist[lo + pos];
                e0   = g_rowptr[node];
                deg  = g_rowptr[node + 1] - e0;
                xv   = g_x[node * 64 + f];
                if (deg <= 64 && f < deg) esh[sub][0][f] = g_csrc[e0 + f];
            }
            bar64(bid);

            for (; pos < cnt; pos += per) {
                float acc0 = xv, acc1 = 0.f, acc2 = 0.f, acc3 = 0.f;
                float acc4 = 0.f, acc5 = 0.f, acc6 = 0.f, acc7 = 0.f;
                if (deg <= 64) {
                    const int* ep = esh[sub][buf];
                    int i = 0;
                    for (; i + 8 <= deg; i += 8) {
                        int s0 = ep[i+0], s1 = ep[i+1], s2 = ep[i+2], s3 = ep[i+3];
                        int s4 = ep[i+4], s5 = ep[i+5], s6 = ep[i+6], s7 = ep[i+7];
                        acc0 += g_x[s0 * 64 + f];
                        acc1 += g_x[s1 * 64 + f];
                        acc2 += g_x[s2 * 64 + f];
                        acc3 += g_x[s3 * 64 + f];
                        acc4 += g_x[s4 * 64 + f];
                        acc5 += g_x[s5 * 64 + f];
                        acc6 += g_x[s6 * 64 + f];
                        acc7 += g_x[s7 * 64 + f];
                    }
                    for (; i < deg; ++i) acc0 += g_x[ep[i] * 64 + f];
                } else {
                    for (int chunk = e0; chunk < e0 + deg; chunk += 64) {
                        int m = min(64, e0 + deg - chunk);
                        if (f < m) esh[sub][buf][f] = g_csrc[chunk + f];
                        bar64(bid);
                        const int* ep = esh[sub][buf];
                        int i = 0;
                        for (; i + 8 <= m; i += 8) {
                            int s0 = ep[i+0], s1 = ep[i+1], s2 = ep[i+2], s3 = ep[i+3];
                            int s4 = ep[i+4], s5 = ep[i+5], s6 = ep[i+6], s7 = ep[i+7];
                            acc0 += g_x[s0 * 64 + f];
                            acc1 += g_x[s1 * 64 + f];
                            acc2 += g_x[s2 * 64 + f];
                            acc3 += g_x[s3 * 64 + f];
                            acc4 += g_x[s4 * 64 + f];
                            acc5 += g_x[s5 * 64 + f];
                            acc6 += g_x[s6 * 64 + f];
                            acc7 += g_x[s7 * 64 + f];
                        }
                        for (; i < m; ++i) acc0 += g_x[ep[i] * 64 + f];
                        bar64(bid);
                    }
                }
                hsh[sub][f] = ((acc0 + acc1) + (acc2 + acc3)) + ((acc4 + acc5) + (acc6 + acc7));

                int npos = pos + per;
                int nnode = 0, ne0 = 0, ndeg = 0;
                float nxv = 0.f;
                if (npos < cnt) {
                    nnode = g_clist[lo + npos];
                    ne0   = g_rowptr[nnode];
                    ndeg  = g_rowptr[nnode + 1] - ne0;
                    nxv   = g_x[nnode * 64 + f];
                    if (ndeg <= 64 && f < ndeg) esh[sub][buf ^ 1][f] = g_csrc[ne0 + f];
                }
                bar64(bid);
                float o0 = 0.f, o1 = 0.f, o2 = 0.f, o3 = 0.f;
#pragma unroll
                for (int i = 0; i < 16; ++i) {
                    o0 += hsh[sub][i]      * wcol[i];
                    o1 += hsh[sub][i + 16] * wcol[i + 16];
                    o2 += hsh[sub][i + 32] * wcol[i + 32];
                    o3 += hsh[sub][i + 48] * wcol[i + 48];
                }
                float o = bias + ((o0 + o1) + (o2 + o3));
                g_h[node * 64 + f] = o;
                a1 += o; a2 += o * o;
                bar64(bid);

                node = nnode; e0 = ne0; deg = ndeg; xv = nxv; buf ^= 1;
            }
            atomicAdd(&s1sh[f], a1);
            atomicAdd(&s2sh[f], a2);
            __syncthreads();
            if (tid < 64) {
                atomicAdd(&g_stats[tc * 128 + tid],      s1sh[tid]);
                atomicAdd(&g_stats[tc * 128 + 64 + tid], s2sh[tid]);
            }
            grid_barrier();

            // === phase B: BN + ReLU + mm2, write back x ===
#pragma unroll
            for (int i = 0; i < 64; ++i) wcol[i] = Wsh2[i * 64 + f];
            float bias2 = b2[tc * 64 + f];
            float cnt_f = (float)max(cnt, 1);
            float mean  = g_stats[tc * 128 + f] / cnt_f;
            float var   = g_stats[tc * 128 + 64 + f] / cnt_f - mean * mean;
            float inv   = rsqrtf(var + 1e-5f) * g1[tc * 64 + f];
            float beta  = be1[tc * 64 + f];

            pos = b * 4 + sub;
            int node2 = 0;
            float hv = 0.f;
            if (pos < cnt) {
                node2 = g_clist[lo + pos];
                hv    = g_h[node2 * 64 + f];
            }
            for (; pos < cnt; pos += per) {
                hsh[sub][f] = fmaxf((hv - mean) * inv + beta, 0.f);
                int npos = pos + per;
                int nnode = 0;
                float nhv = 0.f;
                if (npos < cnt) {
                    nnode = g_clist[lo + npos];
                    nhv   = g_h[nnode * 64 + f];
                }
                bar64(bid);
                float o0 = 0.f, o1 = 0.f, o2 = 0.f, o3 = 0.f;
#pragma unroll
                for (int i = 0; i < 16; ++i) {
                    o0 += hsh[sub][i]      * wcol[i];
                    o1 += hsh[sub][i + 16] * wcol[i + 16];
                    o2 += hsh[sub][i + 32] * wcol[i + 32];
                    o3 += hsh[sub][i + 48] * wcol[i + 48];
                }
                g_x[node2 * 64 + f] = bias2 + ((o0 + o1) + (o2 + o3));
                bar64(bid);
                node2 = nnode; hv = nhv;
            }
            grid_barrier();
        }

        // ---- pooling for layer t: 256 blocks = 64 graphs x 4 chunks ----
        if (b < GG * 4) {
            const int g  = b >> 2;
            const int ch = b & 3;
            int* lohi = (int*)esh;
            if (tid < 2) {
                int target = g + tid;
                int lo2 = 0, hi2 = NN;
                while (lo2 < hi2) {
                    int m = (lo2 + hi2) >> 1;
                    if (load_idx(batch, m, is64) < target) lo2 = m + 1; else hi2 = m;
                }
                lohi[tid] = lo2;
            }
            __syncthreads();
            int lo2 = lohi[0], hi2 = lohi[1];
            int len = hi2 - lo2;
            int clo = lo2 + ((len * ch) >> 2);
            int chi = lo2 + ((len * (ch + 1)) >> 2);
            float s0 = 0.f, s1 = 0.f;
            int r = clo + sub;
            for (; r + 8 <= chi; r += 8) {
                s0 += g_x[r * 64 + f];
                s1 += g_x[(r + 4) * 64 + f];
            }
            for (; r < chi; r += 4) s0 += g_x[r * 64 + f];
            hsh[sub][f] = s0 + s1;
            __syncthreads();
            if (sub == 0) {
                float v = hsh[0][f] + hsh[1][f] + hsh[2][f] + hsh[3][f];
                atomicAdd(&g_z[g * (HH * LL) + t * 64 + f], v);
            }
        }
        grid_barrier();
    }

    // ---- F1: h1[g] = z[g] @ Wp1 + bp1  (64 blocks, one graph row each) ----
    if (b < GG) {
        float* zsh = Wsh1;          // reuse: 192 floats
        if (tid < HH * LL) zsh[tid] = g_z[b * (HH * LL) + tid];
        __syncthreads();
        float p = 0.f;
        int k0 = sub * 48;
#pragma unroll
        for (int k = 0; k < 48; ++k) p += zsh[k0 + k] * Wp1[(k0 + k) * 64 + f];
        hsh[sub][f] = p;
        __syncthreads();
        if (sub == 0)
            g_h1[b * 64 + f] = bp1[f] + ((hsh[0][f] + hsh[1][f]) + (hsh[2][f] + hsh[3][f]));
    }
    grid_barrier();

    // ---- F2: BN stats over the 64 graph rows (block 0) ----
    if (b == 0 && tid < 64) {
        float s = 0.f, q = 0.f;
        for (int g = 0; g < GG; ++g) { float v = g_h1[g * 64 + tid]; s += v; q += v * v; }
        float mean = s / (float)GG;
        float var  = q / (float)GG - mean * mean;
        g_bnp[tid]      = mean;
        g_bnp[64 + tid] = rsqrtf(var + 1e-5f) * gp[tid];
    }
    grid_barrier();

    // ---- F3: out[g] = relu(bn(h1[g])) @ Wp2 + bp2  (64 blocks) ----
    if (b < GG) {
        float* vsh = Wsh1;          // reuse: 64 floats
        if (tid < 64) {
            float v = g_h1[b * 64 + tid];
            vsh[tid] = fmaxf((v - g_bnp[tid]) * g_bnp[64 + tid] + bep[tid], 0.f);
        }
        __syncthreads();
        float p = 0.f;
        int k0 = sub * 16;
#pragma unroll
        for (int k = 0; k < 16; ++k) p += vsh[k0 + k] * Wp2[(k0 + k) * 64 + f];
        hsh[sub][f] = p;
        __syncthreads();
        if (sub == 0)
            out[b * 64 + f] = bp2[f] + ((hsh[0][f] + hsh[1][f]) + (hsh[2][f] + hsh[3][f]));
    }
}

// ---------------------------------------------------------------------------
extern "C" void kernel_launch(void* const* d_in, const int* in_sizes, int n_in,
                              void* d_out, int out_size) {
    const float* x     = (const float*)d_in[0];
    const int*   cl    = (const int*)d_in[1];
    const void*  eidx  = d_in[2];
    const void*  batch = d_in[3];
    const float* W1  = (const float*)d_in[4];
    const float* b1  = (const float*)d_in[5];
    const float* g1  = (const float*)d_in[6];
    const float* be1 = (const float*)d_in[7];
    const float* W2  = (const float*)d_in[8];
    const float* b2  = (const float*)d_in[9];
    const float* Wp1 = (const float*)d_in[10];
    const float* bp1 = (const float*)d_in[11];
    const float* gp  = (const float*)d_in[12];
    const float* bep = (const float*)d_in[13];
    const float* Wp2 = (const float*)d_in[14];
    const float* bp2 = (const float*)d_in[15];
    float* out = (float*)d_out;

    persistent_kernel<<<NB, NT>>>(x, cl, eidx, batch, W1, b1, g1, be1, W2, b2,
                                  Wp1, bp1, gp, bep, Wp2, bp2, out);
}